// round 1
// baseline (speedup 1.0000x reference)
#include <cuda_runtime.h>
#include <math.h>

#define NTOK 2048
#define HIDDIM 2048
#define NH 32
#define DKD 128
#define CONVK 4
#define PROJ (NH*DKD)      // 4096
#define VSPLIT 4
#define VCOLS (DKD/VSPLIT) // 32

// ---------------- scratch (static device arrays; no allocations) ----------------
__device__ float g_qpre[(size_t)NTOK*PROJ];
__device__ float g_kpre[(size_t)NTOK*PROJ];   // reused as `core` after conv
__device__ float g_vpre[(size_t)NTOK*PROJ];
__device__ float g_qb [(size_t)NTOK*PROJ];
__device__ float g_kb [(size_t)NTOK*PROJ];
__device__ float g_vb [(size_t)NTOK*PROJ];
__device__ float g_gb [(size_t)NTOK*PROJ];    // f, then g in-place
__device__ float g_gate[(size_t)NTOK*PROJ];
__device__ float g_fa [(size_t)NTOK*DKD];
__device__ float g_ga [(size_t)NTOK*DKD];
__device__ float g_betapre[(size_t)NTOK*NH];
__device__ float g_beta   [(size_t)NTOK*NH];

// ---------------- packed fp32x2 helpers (exact fp32 semantics, 2x issue) --------
__device__ __forceinline__ unsigned long long pack2(float x, float y) {
    unsigned long long r;
    asm("mov.b64 %0, {%1,%2};" : "=l"(r) : "f"(x), "f"(y));
    return r;
}
__device__ __forceinline__ unsigned long long fma2(unsigned long long a,
                                                   unsigned long long b,
                                                   unsigned long long c) {
    unsigned long long d;
    asm("fma.rn.f32x2 %0, %1, %2, %3;" : "=l"(d) : "l"(a), "l"(b), "l"(c));
    return d;
}
__device__ __forceinline__ float2 unpack2(unsigned long long v) {
    float2 f;
    asm("mov.b64 {%0,%1}, %2;" : "=f"(f.x), "=f"(f.y) : "l"(v));
    return f;
}

// ---------------- GEMM: C[M,N] = A[M,K] * B[N,K]^T  (both row-major, K-contig) ---
// 64x64 tile, BK=16, 256 threads, 4x4 micro-tile per thread via f32x2 FMA.
__global__ __launch_bounds__(256) void sgemm_nt(const float* __restrict__ A,
                                                const float* __restrict__ B,
                                                float* __restrict__ C,
                                                int M, int Nn, int K)
{
    __shared__ unsigned long long As2[16][64];   // A values duplicated into pairs
    __shared__ unsigned long long Bsu[16][32];   // 64 floats per row as 32 pairs

    const int tid = threadIdx.x;
    const int tx = tid & 15, ty = tid >> 4;
    const int lr = tid >> 2;          // 0..63 (row within tile)
    const int lc = (tid & 3) << 2;    // 0,4,8,12 (k within tile)

    const long arow = (long)blockIdx.y * 64 + lr;
    const long brow = (long)blockIdx.x * 64 + lr;
    const float* Ap = A + arow * K + lc;
    const float* Bp = B + brow * K + lc;
    const bool bok = brow < Nn;
    float* Bf = reinterpret_cast<float*>(&Bsu[0][0]);

    unsigned long long acc[4][2];
#pragma unroll
    for (int j = 0; j < 4; j++) { acc[j][0] = 0ull; acc[j][1] = 0ull; }

    for (int k0 = 0; k0 < K; k0 += 16) {
        float4 av = *reinterpret_cast<const float4*>(Ap + k0);
        float4 bv = bok ? *reinterpret_cast<const float4*>(Bp + k0)
                        : make_float4(0.f, 0.f, 0.f, 0.f);
        As2[lc + 0][lr] = pack2(av.x, av.x);
        As2[lc + 1][lr] = pack2(av.y, av.y);
        As2[lc + 2][lr] = pack2(av.z, av.z);
        As2[lc + 3][lr] = pack2(av.w, av.w);
        Bf[(lc + 0) * 64 + lr] = bv.x;
        Bf[(lc + 1) * 64 + lr] = bv.y;
        Bf[(lc + 2) * 64 + lr] = bv.z;
        Bf[(lc + 3) * 64 + lr] = bv.w;
        __syncthreads();

#pragma unroll
        for (int kk = 0; kk < 16; kk++) {
            unsigned long long b0 = Bsu[kk][tx * 2];
            unsigned long long b1 = Bsu[kk][tx * 2 + 1];
#pragma unroll
            for (int j = 0; j < 4; j++) {
                unsigned long long ad = As2[kk][ty * 4 + j];
                acc[j][0] = fma2(ad, b0, acc[j][0]);
                acc[j][1] = fma2(ad, b1, acc[j][1]);
            }
        }
        __syncthreads();
    }

    const int crow = blockIdx.y * 64 + ty * 4;
    const int ccol = blockIdx.x * 64 + tx * 4;
    if (ccol < Nn) {
#pragma unroll
        for (int j = 0; j < 4; j++) {
            float2 c01 = unpack2(acc[j][0]);
            float2 c23 = unpack2(acc[j][1]);
            float4 o = make_float4(c01.x, c01.y, c23.x, c23.y);
            *reinterpret_cast<float4*>(C + (long)(crow + j) * Nn + ccol) = o;
        }
    }
}

// ---------------- depthwise causal conv (K=4) + SiLU ----------------------------
__global__ __launch_bounds__(256) void conv_silu_kernel(const float* __restrict__ x,
                                                        const float* __restrict__ w,
                                                        float* __restrict__ y)
{
    int idx = blockIdx.x * blockDim.x + threadIdx.x;
    if (idx >= NTOK * PROJ) return;
    int n = idx / PROJ;
    int d = idx - n * PROJ;
    float acc = 0.f;
#pragma unroll
    for (int i = 0; i < CONVK; i++) {
        int nn = n - (CONVK - 1) + i;
        float xv = (nn >= 0) ? x[(long)nn * PROJ + d] : 0.f;
        acc = fmaf(xv, w[d * CONVK + i], acc);
    }
    y[idx] = acc / (1.f + expf(-acc));
}

// ---------------- per-(n,h): l2-normalize q,k; build g; sigmoid(beta) -----------
__global__ __launch_bounds__(128) void prep_kernel(float* __restrict__ q,
                                                   float* __restrict__ k,
                                                   float* __restrict__ g,
                                                   const float* __restrict__ betapre,
                                                   float* __restrict__ beta,
                                                   const float* __restrict__ A_log,
                                                   const float* __restrict__ dt_bias)
{
    const int row = blockIdx.x;          // n*NH + h
    const int hh = row & (NH - 1);
    const int tid = threadIdx.x;         // 0..127 = dk
    const long base = (long)row * DKD;   // (n*NH+h)*DK == n*PROJ + h*DK

    float qv = q[base + tid];
    float kv = k[base + tid];
    float sq = qv * qv, sk = kv * kv;
#pragma unroll
    for (int o = 16; o > 0; o >>= 1) {
        sq += __shfl_xor_sync(0xffffffffu, sq, o);
        sk += __shfl_xor_sync(0xffffffffu, sk, o);
    }
    __shared__ float red[4][2];
    int wid = tid >> 5, lane = tid & 31;
    if (lane == 0) { red[wid][0] = sq; red[wid][1] = sk; }
    __syncthreads();
    float sumq = red[0][0] + red[1][0] + red[2][0] + red[3][0];
    float sumk = red[0][1] + red[1][1] + red[2][1] + red[3][1];

    q[base + tid] = qv * rsqrtf(sumq + 1e-6f) * 0.08838834764831845f; // * dk^-0.5
    k[base + tid] = kv * rsqrtf(sumk + 1e-6f);

    float fv = g[base + tid] + dt_bias[hh * DKD + tid];
    float sp = (fv > 20.f) ? fv : log1pf(expf(fv));
    g[base + tid] = -expf(A_log[hh]) * sp;

    if (tid == 0) beta[row] = 1.f / (1.f + expf(-betapre[row]));
}

// ---------------- sequential gated delta-rule scan ------------------------------
// grid = NH*VSPLIT CTAs; CTA owns head h, value columns [vb, vb+32).
// 256 threads: v = tid&31, key-group kg = tid>>5 (16 keys each), state in regs.
__global__ __launch_bounds__(256) void scan_kernel(const float* __restrict__ q,
                                                   const float* __restrict__ k,
                                                   const float* __restrict__ v,
                                                   const float* __restrict__ g,
                                                   const float* __restrict__ beta,
                                                   float* __restrict__ core)
{
    const int h  = blockIdx.x / VSPLIT;
    const int vb = (blockIdx.x % VSPLIT) * VCOLS;
    const int tid = threadIdx.x;
    const int vc = tid & 31;
    const int kg = tid >> 5;
    const int kbase = kg * 16;

    __shared__ float sk[DKD], sq[DKD], seg[DKD];
    __shared__ float sv[VCOLS], sdelta[VCOLS];
    __shared__ float red[8][VCOLS];
    __shared__ float sbeta;

    float s[16];
#pragma unroll
    for (int i = 0; i < 16; i++) s[i] = 0.f;

    const int hb = h * DKD;
    for (int t = 0; t < NTOK; t++) {
        const long off = (long)t * PROJ + hb;
        if (tid < DKD) {
            sk[tid] = k[off + tid];
            sq[tid] = q[off + tid];
            seg[tid] = expf(g[off + tid]);
        } else if (tid < DKD + VCOLS) {
            sv[tid - DKD] = v[off + vb + (tid - DKD)];
        } else if (tid == DKD + VCOLS) {
            sbeta = beta[t * NH + h];
        }
        __syncthreads();

        float kreg[16];
        float acc = 0.f;
#pragma unroll
        for (int i = 0; i < 16; i++) {
            int kk = kbase + i;
            float kv_ = sk[kk];
            kreg[i] = kv_;
            float sn = s[i] * seg[kk];
            s[i] = sn;
            acc = fmaf(kv_, sn, acc);
        }
        red[kg][vc] = acc;
        __syncthreads();

        if (kg == 0) {
            float kvs = red[0][vc] + red[1][vc] + red[2][vc] + red[3][vc]
                      + red[4][vc] + red[5][vc] + red[6][vc] + red[7][vc];
            sdelta[vc] = (sv[vc] - kvs) * sbeta;
        }
        __syncthreads();

        float delta = sdelta[vc];
        float oacc = 0.f;
#pragma unroll
        for (int i = 0; i < 16; i++) {
            int kk = kbase + i;
            float sn = fmaf(kreg[i], delta, s[i]);
            s[i] = sn;
            oacc = fmaf(sq[kk], sn, oacc);
        }
        red[kg][vc] = oacc;
        __syncthreads();

        if (kg == 0) {
            float osum = red[0][vc] + red[1][vc] + red[2][vc] + red[3][vc]
                       + red[4][vc] + red[5][vc] + red[6][vc] + red[7][vc];
            core[off + vb + vc] = osum;
        }
        __syncthreads();
    }
}

// ---------------- gated RMSNorm (sigmoid gate) -----------------------------------
__global__ __launch_bounds__(128) void rmsgate_kernel(const float* __restrict__ core,
                                                      const float* __restrict__ gate,
                                                      const float* __restrict__ onorm_w,
                                                      float* __restrict__ rg)
{
    const int row = blockIdx.x;          // n*NH + h
    const int tid = threadIdx.x;
    const long base = (long)row * DKD;

    float c = core[base + tid];
    float ss = c * c;
#pragma unroll
    for (int o = 16; o > 0; o >>= 1)
        ss += __shfl_xor_sync(0xffffffffu, ss, o);
    __shared__ float red[4];
    int wid = tid >> 5, lane = tid & 31;
    if (lane == 0) red[wid] = ss;
    __syncthreads();
    float sum = red[0] + red[1] + red[2] + red[3];

    float rms = c * rsqrtf(sum * (1.f / DKD) + 1e-5f);
    float gt = gate[base + tid];
    rg[base + tid] = rms * onorm_w[tid] * (1.f / (1.f + expf(-gt)));
}

// ---------------- launch ---------------------------------------------------------
extern "C" void kernel_launch(void* const* d_in, const int* in_sizes, int n_in,
                              void* d_out, int out_size)
{
    const float* hs   = (const float*)d_in[0];
    const float* Wq   = (const float*)d_in[1];
    const float* Wk   = (const float*)d_in[2];
    const float* Wv   = (const float*)d_in[3];
    const float* cq   = (const float*)d_in[4];
    const float* ck   = (const float*)d_in[5];
    const float* cv   = (const float*)d_in[6];
    const float* Wfa  = (const float*)d_in[7];
    const float* Wfb  = (const float*)d_in[8];
    const float* dtb  = (const float*)d_in[9];
    const float* Wb   = (const float*)d_in[10];
    const float* Alog = (const float*)d_in[11];
    const float* Wga  = (const float*)d_in[12];
    const float* Wgb  = (const float*)d_in[13];
    const float* onw  = (const float*)d_in[14];
    const float* Wo   = (const float*)d_in[15];
    float* out = (float*)d_out;

    float *qpre, *kpre, *vpre, *qb, *kb, *vbuf, *gb, *gateb, *fa, *ga, *betapre, *betab;
    cudaGetSymbolAddress((void**)&qpre, g_qpre);
    cudaGetSymbolAddress((void**)&kpre, g_kpre);
    cudaGetSymbolAddress((void**)&vpre, g_vpre);
    cudaGetSymbolAddress((void**)&qb,   g_qb);
    cudaGetSymbolAddress((void**)&kb,   g_kb);
    cudaGetSymbolAddress((void**)&vbuf, g_vb);
    cudaGetSymbolAddress((void**)&gb,   g_gb);
    cudaGetSymbolAddress((void**)&gateb,g_gate);
    cudaGetSymbolAddress((void**)&fa,   g_fa);
    cudaGetSymbolAddress((void**)&ga,   g_ga);
    cudaGetSymbolAddress((void**)&betapre, g_betapre);
    cudaGetSymbolAddress((void**)&betab,   g_beta);

    float* core = kpre;  // kpre dead after conv
    float* rg   = qpre;  // qpre dead after conv

    dim3 blk(256);
    auto gg = [](int M, int Nn) { return dim3((unsigned)((Nn + 63) / 64), (unsigned)((M + 63) / 64)); };

    // projections
    sgemm_nt<<<gg(NTOK, PROJ), blk>>>(hs, Wq, qpre, NTOK, PROJ, HIDDIM);
    sgemm_nt<<<gg(NTOK, PROJ), blk>>>(hs, Wk, kpre, NTOK, PROJ, HIDDIM);
    sgemm_nt<<<gg(NTOK, PROJ), blk>>>(hs, Wv, vpre, NTOK, PROJ, HIDDIM);
    sgemm_nt<<<gg(NTOK, DKD),  blk>>>(hs, Wfa, fa, NTOK, DKD, HIDDIM);
    sgemm_nt<<<gg(NTOK, NH),   blk>>>(hs, Wb, betapre, NTOK, NH, HIDDIM);
    sgemm_nt<<<gg(NTOK, DKD),  blk>>>(hs, Wga, ga, NTOK, DKD, HIDDIM);

    // conv + silu (frees kpre/qpre for reuse)
    int ce = NTOK * PROJ;
    conv_silu_kernel<<<(ce + 255) / 256, 256>>>(qpre, cq, qb);
    conv_silu_kernel<<<(ce + 255) / 256, 256>>>(kpre, ck, kb);
    conv_silu_kernel<<<(ce + 255) / 256, 256>>>(vpre, cv, vbuf);

    // low-rank expansions
    sgemm_nt<<<gg(NTOK, PROJ), blk>>>(fa, Wfb, gb,    NTOK, PROJ, DKD);
    sgemm_nt<<<gg(NTOK, PROJ), blk>>>(ga, Wgb, gateb, NTOK, PROJ, DKD);

    // normalize q/k, build g and beta
    prep_kernel<<<NTOK * NH, 128>>>(qb, kb, gb, betapre, betab, Alog, dtb);

    // recurrent delta-rule scan
    scan_kernel<<<NH * VSPLIT, 256>>>(qb, kb, vbuf, gb, betab, core);

    // gated rmsnorm
    rmsgate_kernel<<<NTOK * NH, 128>>>(core, gateb, onw, rg);

    // output projection
    sgemm_nt<<<gg(NTOK, HIDDIM), blk>>>(rg, Wo, out, NTOK, HIDDIM, PROJ);
}

// round 11
// speedup vs baseline: 1.8777x; 1.8777x over previous
#include <cuda_runtime.h>
#include <cuda_bf16.h>
#include <math.h>

#define NTOK 2048
#define HIDDIM 2048
#define NH 32
#define DKD 128
#define CONVK 4
#define PROJ (NH*DKD)      // 4096
#define VSPLIT 4
#define VCOLS (DKD/VSPLIT) // 32

// ---------------- scratch (static device arrays; no allocations) ----------------
__device__ float g_qpre[(size_t)NTOK*PROJ];
__device__ float g_kpre[(size_t)NTOK*PROJ];   // reused as `core` after conv
__device__ float g_vpre[(size_t)NTOK*PROJ];
__device__ float g_qb [(size_t)NTOK*PROJ];
__device__ float g_kb [(size_t)NTOK*PROJ];
__device__ float g_vb [(size_t)NTOK*PROJ];
__device__ float g_gb [(size_t)NTOK*PROJ];    // f, then g in-place
__device__ float g_gate[(size_t)NTOK*PROJ];
__device__ float g_fa [(size_t)NTOK*DKD];
__device__ float g_ga [(size_t)NTOK*DKD];
__device__ float g_betapre[(size_t)NTOK*NH];
__device__ float g_beta   [(size_t)NTOK*NH];

// ================= bf16-split HMMA GEMM (mma.sync, baseline PTX) =================
// C[M,N] = A[M,K] * B[N,K]^T, fp32 in/out, fp32-class accuracy via 3-pass bf16 split.
#define BM 128
#define BN 128
#define BK 32
#define SST 40          // smem row stride in bf16 elems (80B, 16B-aligned, conflict-light)

__device__ __forceinline__ void ldsm4(unsigned* r, unsigned addr) {
    asm volatile("ldmatrix.sync.aligned.m8n8.x4.shared.b16 {%0,%1,%2,%3}, [%4];"
                 : "=r"(r[0]), "=r"(r[1]), "=r"(r[2]), "=r"(r[3]) : "r"(addr));
}

__device__ __forceinline__ void mma16816(float* c, const unsigned* a,
                                         unsigned b0, unsigned b1) {
    asm volatile(
        "mma.sync.aligned.m16n8k16.row.col.f32.bf16.bf16.f32 "
        "{%0,%1,%2,%3}, {%4,%5,%6,%7}, {%8,%9}, {%0,%1,%2,%3};"
        : "+f"(c[0]), "+f"(c[1]), "+f"(c[2]), "+f"(c[3])
        : "r"(a[0]), "r"(a[1]), "r"(a[2]), "r"(a[3]), "r"(b0), "r"(b1));
}

__device__ __forceinline__ void split2(float x, float y, unsigned& hi, unsigned& lo) {
    __nv_bfloat16 hx = __float2bfloat16_rn(x);
    __nv_bfloat16 hy = __float2bfloat16_rn(y);
    hi = (unsigned)__bfloat16_as_ushort(hx) |
         ((unsigned)__bfloat16_as_ushort(hy) << 16);
    float rx = x - __bfloat162float(hx);
    float ry = y - __bfloat162float(hy);
    lo = (unsigned)__bfloat16_as_ushort(__float2bfloat16_rn(rx)) |
         ((unsigned)__bfloat16_as_ushort(__float2bfloat16_rn(ry)) << 16);
}

__global__ __launch_bounds__(256) void hgemm_nt(const float* __restrict__ A,
                                                const float* __restrict__ B,
                                                float* __restrict__ C,
                                                int M, int Nn, int K)
{
    __shared__ unsigned short As_hi[BM * SST];
    __shared__ unsigned short As_lo[BM * SST];
    __shared__ unsigned short Bs_hi[BN * SST];
    __shared__ unsigned short Bs_lo[BN * SST];

    const int tid = threadIdx.x;
    const int lane = tid & 31;
    const int wid = tid >> 5;
    const int wm = wid >> 2;          // 0..1 -> m offset 64
    const int wn = wid & 3;           // 0..3 -> n offset 32
    const int mtile = blockIdx.y, ntile = blockIdx.x;

    const unsigned ahi = (unsigned)__cvta_generic_to_shared(As_hi);
    const unsigned alo = (unsigned)__cvta_generic_to_shared(As_lo);
    const unsigned bhi = (unsigned)__cvta_generic_to_shared(Bs_hi);
    const unsigned blo = (unsigned)__cvta_generic_to_shared(Bs_lo);

    // global tile load mapping: idx = tid + i*256 -> row = idx>>3, col = (idx&7)*4
    int lrow[4], lcol[4];
#pragma unroll
    for (int i = 0; i < 4; i++) {
        int idx = tid + i * 256;
        lrow[i] = idx >> 3;
        lcol[i] = (idx & 7) << 2;
    }
    const float* Ag = A + (size_t)(mtile * BM) * K;
    const float* Bg = B + (size_t)(ntile * BN) * K;

    float acc[4][4][4];
#pragma unroll
    for (int a = 0; a < 4; a++)
#pragma unroll
        for (int b = 0; b < 4; b++)
#pragma unroll
            for (int cc = 0; cc < 4; cc++) acc[a][b][cc] = 0.f;

    // fragment smem addresses (bytes)
    unsigned a_row = wm * 64 + (lane & 15);
    unsigned a_half = (lane >> 4) * 8;
    unsigned b_row = wn * 32 + (lane & 15);

    const int NC = K / BK;
    float4 bufA[4], bufB[4];

    // prefetch chunk 0
#pragma unroll
    for (int i = 0; i < 4; i++) {
        bufA[i] = *reinterpret_cast<const float4*>(Ag + (size_t)lrow[i] * K + lcol[i]);
        int grow = ntile * BN + lrow[i];
        bufB[i] = (grow < Nn)
                      ? *reinterpret_cast<const float4*>(Bg + (size_t)lrow[i] * K + lcol[i])
                      : make_float4(0.f, 0.f, 0.f, 0.f);
    }

    for (int c = 0; c < NC; c++) {
        // convert + store to smem
#pragma unroll
        for (int i = 0; i < 4; i++) {
            unsigned h0, l0, h1, l1;
            split2(bufA[i].x, bufA[i].y, h0, l0);
            split2(bufA[i].z, bufA[i].w, h1, l1);
            unsigned off = (unsigned)(lrow[i] * SST + lcol[i]) * 2;
            asm volatile("st.shared.v2.b32 [%0], {%1,%2};" :: "r"(ahi + off), "r"(h0), "r"(h1));
            asm volatile("st.shared.v2.b32 [%0], {%1,%2};" :: "r"(alo + off), "r"(l0), "r"(l1));
            split2(bufB[i].x, bufB[i].y, h0, l0);
            split2(bufB[i].z, bufB[i].w, h1, l1);
            asm volatile("st.shared.v2.b32 [%0], {%1,%2};" :: "r"(bhi + off), "r"(h0), "r"(h1));
            asm volatile("st.shared.v2.b32 [%0], {%1,%2};" :: "r"(blo + off), "r"(l0), "r"(l1));
        }
        __syncthreads();

        // prefetch next chunk (overlaps with mma below)
        if (c + 1 < NC) {
            int k0 = (c + 1) * BK;
#pragma unroll
            for (int i = 0; i < 4; i++) {
                bufA[i] = *reinterpret_cast<const float4*>(Ag + (size_t)lrow[i] * K + k0 + lcol[i]);
                int grow = ntile * BN + lrow[i];
                bufB[i] = (grow < Nn)
                              ? *reinterpret_cast<const float4*>(Bg + (size_t)lrow[i] * K + k0 + lcol[i])
                              : make_float4(0.f, 0.f, 0.f, 0.f);
            }
        }

#pragma unroll
        for (int ks = 0; ks < 2; ks++) {
            unsigned kk = ks * 16 + a_half;
            unsigned afr[4][4], bh2[2][4], bl2[2][4];
#pragma unroll
            for (int mt = 0; mt < 4; mt++)
                ldsm4(afr[mt], ahi + ((a_row + mt * 16) * SST + kk) * 2);
#pragma unroll
            for (int p = 0; p < 2; p++) {
                ldsm4(bh2[p], bhi + ((b_row + p * 16) * SST + kk) * 2);
                ldsm4(bl2[p], blo + ((b_row + p * 16) * SST + kk) * 2);
            }
            // pass 1: Ahi * Bhi
#pragma unroll
            for (int mt = 0; mt < 4; mt++)
#pragma unroll
                for (int nt = 0; nt < 4; nt++)
                    mma16816(acc[mt][nt], afr[mt],
                             bh2[nt >> 1][nt & 1], bh2[nt >> 1][2 + (nt & 1)]);
            // pass 2: Ahi * Blo
#pragma unroll
            for (int mt = 0; mt < 4; mt++)
#pragma unroll
                for (int nt = 0; nt < 4; nt++)
                    mma16816(acc[mt][nt], afr[mt],
                             bl2[nt >> 1][nt & 1], bl2[nt >> 1][2 + (nt & 1)]);
            // pass 3: Alo * Bhi
#pragma unroll
            for (int mt = 0; mt < 4; mt++)
                ldsm4(afr[mt], alo + ((a_row + mt * 16) * SST + kk) * 2);
#pragma unroll
            for (int mt = 0; mt < 4; mt++)
#pragma unroll
                for (int nt = 0; nt < 4; nt++)
                    mma16816(acc[mt][nt], afr[mt],
                             bh2[nt >> 1][nt & 1], bh2[nt >> 1][2 + (nt & 1)]);
        }
        __syncthreads();
    }

    // epilogue
#pragma unroll
    for (int mt = 0; mt < 4; mt++) {
        int grow = mtile * BM + wm * 64 + mt * 16 + (lane >> 2);
#pragma unroll
        for (int nt = 0; nt < 4; nt++) {
            int gcol = ntile * BN + wn * 32 + nt * 8 + (lane & 3) * 2;
            if (gcol < Nn) {
                float2 v0 = make_float2(acc[mt][nt][0], acc[mt][nt][1]);
                float2 v1 = make_float2(acc[mt][nt][2], acc[mt][nt][3]);
                *reinterpret_cast<float2*>(C + (size_t)grow * Nn + gcol) = v0;
                *reinterpret_cast<float2*>(C + (size_t)(grow + 8) * Nn + gcol) = v1;
            }
        }
    }
}

// ---------------- depthwise causal conv (K=4) + SiLU ----------------------------
__global__ __launch_bounds__(256) void conv_silu_kernel(const float* __restrict__ x,
                                                        const float* __restrict__ w,
                                                        float* __restrict__ y)
{
    int idx = blockIdx.x * blockDim.x + threadIdx.x;
    if (idx >= NTOK * PROJ) return;
    int n = idx / PROJ;
    int d = idx - n * PROJ;
    float acc = 0.f;
#pragma unroll
    for (int i = 0; i < CONVK; i++) {
        int nn = n - (CONVK - 1) + i;
        float xv = (nn >= 0) ? x[(long)nn * PROJ + d] : 0.f;
        acc = fmaf(xv, w[d * CONVK + i], acc);
    }
    y[idx] = acc / (1.f + expf(-acc));
}

// ---------------- per-(n,h): l2-normalize q,k; build g; sigmoid(beta) -----------
__global__ __launch_bounds__(128) void prep_kernel(float* __restrict__ q,
                                                   float* __restrict__ k,
                                                   float* __restrict__ g,
                                                   const float* __restrict__ betapre,
                                                   float* __restrict__ beta,
                                                   const float* __restrict__ A_log,
                                                   const float* __restrict__ dt_bias)
{
    const int row = blockIdx.x;          // n*NH + h
    const int hh = row & (NH - 1);
    const int tid = threadIdx.x;         // 0..127 = dk
    const long base = (long)row * DKD;

    float qv = q[base + tid];
    float kv = k[base + tid];
    float sq = qv * qv, sk = kv * kv;
#pragma unroll
    for (int o = 16; o > 0; o >>= 1) {
        sq += __shfl_xor_sync(0xffffffffu, sq, o);
        sk += __shfl_xor_sync(0xffffffffu, sk, o);
    }
    __shared__ float red[4][2];
    int wid = tid >> 5, lane = tid & 31;
    if (lane == 0) { red[wid][0] = sq; red[wid][1] = sk; }
    __syncthreads();
    float sumq = red[0][0] + red[1][0] + red[2][0] + red[3][0];
    float sumk = red[0][1] + red[1][1] + red[2][1] + red[3][1];

    q[base + tid] = qv * rsqrtf(sumq + 1e-6f) * 0.08838834764831845f; // * dk^-0.5
    k[base + tid] = kv * rsqrtf(sumk + 1e-6f);

    float fv = g[base + tid] + dt_bias[hh * DKD + tid];
    float sp = (fv > 20.f) ? fv : log1pf(expf(fv));
    g[base + tid] = -expf(A_log[hh]) * sp;

    if (tid == 0) beta[row] = 1.f / (1.f + expf(-betapre[row]));
}

// ---------------- sequential gated delta-rule scan ------------------------------
__global__ __launch_bounds__(256) void scan_kernel(const float* __restrict__ q,
                                                   const float* __restrict__ k,
                                                   const float* __restrict__ v,
                                                   const float* __restrict__ g,
                                                   const float* __restrict__ beta,
                                                   float* __restrict__ core)
{
    const int h  = blockIdx.x / VSPLIT;
    const int vb = (blockIdx.x % VSPLIT) * VCOLS;
    const int tid = threadIdx.x;
    const int vc = tid & 31;
    const int kg = tid >> 5;
    const int kbase = kg * 16;

    __shared__ float sk[DKD], sq[DKD], seg[DKD];
    __shared__ float sv[VCOLS], sdelta[VCOLS];
    __shared__ float red[8][VCOLS];
    __shared__ float sbeta;

    float s[16];
#pragma unroll
    for (int i = 0; i < 16; i++) s[i] = 0.f;

    const int hb = h * DKD;
    for (int t = 0; t < NTOK; t++) {
        const long off = (long)t * PROJ + hb;
        if (tid < DKD) {
            sk[tid] = k[off + tid];
            sq[tid] = q[off + tid];
            seg[tid] = expf(g[off + tid]);
        } else if (tid < DKD + VCOLS) {
            sv[tid - DKD] = v[off + vb + (tid - DKD)];
        } else if (tid == DKD + VCOLS) {
            sbeta = beta[t * NH + h];
        }
        __syncthreads();

        float kreg[16];
        float acc = 0.f;
#pragma unroll
        for (int i = 0; i < 16; i++) {
            int kk = kbase + i;
            float kv_ = sk[kk];
            kreg[i] = kv_;
            float sn = s[i] * seg[kk];
            s[i] = sn;
            acc = fmaf(kv_, sn, acc);
        }
        red[kg][vc] = acc;
        __syncthreads();

        if (kg == 0) {
            float kvs = red[0][vc] + red[1][vc] + red[2][vc] + red[3][vc]
                      + red[4][vc] + red[5][vc] + red[6][vc] + red[7][vc];
            sdelta[vc] = (sv[vc] - kvs) * sbeta;
        }
        __syncthreads();

        float delta = sdelta[vc];
        float oacc = 0.f;
#pragma unroll
        for (int i = 0; i < 16; i++) {
            int kk = kbase + i;
            float sn = fmaf(kreg[i], delta, s[i]);
            s[i] = sn;
            oacc = fmaf(sq[kk], sn, oacc);
        }
        red[kg][vc] = oacc;
        __syncthreads();

        if (kg == 0) {
            float osum = red[0][vc] + red[1][vc] + red[2][vc] + red[3][vc]
                       + red[4][vc] + red[5][vc] + red[6][vc] + red[7][vc];
            core[off + vb + vc] = osum;
        }
        __syncthreads();
    }
}

// ---------------- gated RMSNorm (sigmoid gate) -----------------------------------
__global__ __launch_bounds__(128) void rmsgate_kernel(const float* __restrict__ core,
                                                      const float* __restrict__ gate,
                                                      const float* __restrict__ onorm_w,
                                                      float* __restrict__ rg)
{
    const int row = blockIdx.x;          // n*NH + h
    const int tid = threadIdx.x;
    const long base = (long)row * DKD;

    float c = core[base + tid];
    float ss = c * c;
#pragma unroll
    for (int o = 16; o > 0; o >>= 1)
        ss += __shfl_xor_sync(0xffffffffu, ss, o);
    __shared__ float red[4];
    int wid = tid >> 5, lane = tid & 31;
    if (lane == 0) red[wid] = ss;
    __syncthreads();
    float sum = red[0] + red[1] + red[2] + red[3];

    float rms = c * rsqrtf(sum * (1.f / DKD) + 1e-5f);
    float gt = gate[base + tid];
    rg[base + tid] = rms * onorm_w[tid] * (1.f / (1.f + expf(-gt)));
}

// ---------------- launch ---------------------------------------------------------
extern "C" void kernel_launch(void* const* d_in, const int* in_sizes, int n_in,
                              void* d_out, int out_size)
{
    const float* hs   = (const float*)d_in[0];
    const float* Wq   = (const float*)d_in[1];
    const float* Wk   = (const float*)d_in[2];
    const float* Wv   = (const float*)d_in[3];
    const float* cq   = (const float*)d_in[4];
    const float* ck   = (const float*)d_in[5];
    const float* cv   = (const float*)d_in[6];
    const float* Wfa  = (const float*)d_in[7];
    const float* Wfb  = (const float*)d_in[8];
    const float* dtb  = (const float*)d_in[9];
    const float* Wb   = (const float*)d_in[10];
    const float* Alog = (const float*)d_in[11];
    const float* Wga  = (const float*)d_in[12];
    const float* Wgb  = (const float*)d_in[13];
    const float* onw  = (const float*)d_in[14];
    const float* Wo   = (const float*)d_in[15];
    float* out = (float*)d_out;

    float *qpre, *kpre, *vpre, *qb, *kb, *vbuf, *gb, *gateb, *fa, *ga, *betapre, *betab;
    cudaGetSymbolAddress((void**)&qpre, g_qpre);
    cudaGetSymbolAddress((void**)&kpre, g_kpre);
    cudaGetSymbolAddress((void**)&vpre, g_vpre);
    cudaGetSymbolAddress((void**)&qb,   g_qb);
    cudaGetSymbolAddress((void**)&kb,   g_kb);
    cudaGetSymbolAddress((void**)&vbuf, g_vb);
    cudaGetSymbolAddress((void**)&gb,   g_gb);
    cudaGetSymbolAddress((void**)&gateb,g_gate);
    cudaGetSymbolAddress((void**)&fa,   g_fa);
    cudaGetSymbolAddress((void**)&ga,   g_ga);
    cudaGetSymbolAddress((void**)&betapre, g_betapre);
    cudaGetSymbolAddress((void**)&betab,   g_beta);

    float* core = kpre;  // kpre dead after conv
    float* rg   = qpre;  // qpre dead after conv

    dim3 blk(256);
    auto gg = [](int M, int Nn) {
        return dim3((unsigned)((Nn + BN - 1) / BN), (unsigned)(M / BM));
    };

    // projections (bf16-split HMMA)
    hgemm_nt<<<gg(NTOK, PROJ), blk>>>(hs, Wq, qpre, NTOK, PROJ, HIDDIM);
    hgemm_nt<<<gg(NTOK, PROJ), blk>>>(hs, Wk, kpre, NTOK, PROJ, HIDDIM);
    hgemm_nt<<<gg(NTOK, PROJ), blk>>>(hs, Wv, vpre, NTOK, PROJ, HIDDIM);
    hgemm_nt<<<gg(NTOK, DKD),  blk>>>(hs, Wfa, fa, NTOK, DKD, HIDDIM);
    hgemm_nt<<<gg(NTOK, NH),   blk>>>(hs, Wb, betapre, NTOK, NH, HIDDIM);
    hgemm_nt<<<gg(NTOK, DKD),  blk>>>(hs, Wga, ga, NTOK, DKD, HIDDIM);

    // conv + silu (frees kpre/qpre for reuse)
    int ce = NTOK * PROJ;
    conv_silu_kernel<<<(ce + 255) / 256, 256>>>(qpre, cq, qb);
    conv_silu_kernel<<<(ce + 255) / 256, 256>>>(kpre, ck, kb);
    conv_silu_kernel<<<(ce + 255) / 256, 256>>>(vpre, cv, vbuf);

    // low-rank expansions (K=128)
    hgemm_nt<<<gg(NTOK, PROJ), blk>>>(fa, Wfb, gb,    NTOK, PROJ, DKD);
    hgemm_nt<<<gg(NTOK, PROJ), blk>>>(ga, Wgb, gateb, NTOK, PROJ, DKD);

    // normalize q/k, build g and beta
    prep_kernel<<<NTOK * NH, 128>>>(qb, kb, gb, betapre, betab, Alog, dtb);

    // recurrent delta-rule scan
    scan_kernel<<<NH * VSPLIT, 256>>>(qb, kb, vbuf, gb, betab, core);

    // gated rmsnorm
    rmsgate_kernel<<<NTOK * NH, 128>>>(core, gateb, onw, rg);

    // output projection
    hgemm_nt<<<gg(NTOK, HIDDIM), blk>>>(rg, Wo, out, NTOK, HIDDIM, PROJ);
}

// round 14
// speedup vs baseline: 1.8814x; 1.0020x over previous
#include <cuda_runtime.h>
#include <cuda_bf16.h>
#include <math.h>

#define NTOK 2048
#define HIDDIM 2048
#define NH 32
#define DKD 128
#define CONVK 4
#define PROJ (NH*DKD)      // 4096
#define VSPLIT 4
#define VCOLS (DKD/VSPLIT) // 32

// ---------------- scratch (static device arrays; no allocations) ----------------
__device__ float g_qpre[(size_t)NTOK*PROJ];
__device__ float g_kpre[(size_t)NTOK*PROJ];   // reused as `core` after conv
__device__ float g_vpre[(size_t)NTOK*PROJ];
__device__ float g_qb [(size_t)NTOK*PROJ];
__device__ float g_kb [(size_t)NTOK*PROJ];
__device__ float g_vb [(size_t)NTOK*PROJ];
__device__ float g_gb [(size_t)NTOK*PROJ];    // f, then g in-place
__device__ float g_gate[(size_t)NTOK*PROJ];
__device__ float g_fa [(size_t)NTOK*DKD];
__device__ float g_ga [(size_t)NTOK*DKD];
__device__ float g_betapre[(size_t)NTOK*NH];
__device__ float g_beta   [(size_t)NTOK*NH];

// ================= bf16-split HMMA GEMM (mma.sync, baseline PTX) =================
// C[M,N] = A[M,K] * B[N,K]^T, fp32 in/out, fp32-class accuracy via 3-pass bf16 split.
#define BM 128
#define BN 128
#define BK 32
#define SST 40          // smem row stride in bf16 elems (80B, 16B-aligned, conflict-light)

__device__ __forceinline__ void ldsm4(unsigned* r, unsigned addr) {
    asm volatile("ldmatrix.sync.aligned.m8n8.x4.shared.b16 {%0,%1,%2,%3}, [%4];"
                 : "=r"(r[0]), "=r"(r[1]), "=r"(r[2]), "=r"(r[3]) : "r"(addr));
}

__device__ __forceinline__ void mma16816(float* c, const unsigned* a,
                                         unsigned b0, unsigned b1) {
    asm volatile(
        "mma.sync.aligned.m16n8k16.row.col.f32.bf16.bf16.f32 "
        "{%0,%1,%2,%3}, {%4,%5,%6,%7}, {%8,%9}, {%0,%1,%2,%3};"
        : "+f"(c[0]), "+f"(c[1]), "+f"(c[2]), "+f"(c[3])
        : "r"(a[0]), "r"(a[1]), "r"(a[2]), "r"(a[3]), "r"(b0), "r"(b1));
}

__device__ __forceinline__ void split2(float x, float y, unsigned& hi, unsigned& lo) {
    __nv_bfloat16 hx = __float2bfloat16_rn(x);
    __nv_bfloat16 hy = __float2bfloat16_rn(y);
    hi = (unsigned)__bfloat16_as_ushort(hx) |
         ((unsigned)__bfloat16_as_ushort(hy) << 16);
    float rx = x - __bfloat162float(hx);
    float ry = y - __bfloat162float(hy);
    lo = (unsigned)__bfloat16_as_ushort(__float2bfloat16_rn(rx)) |
         ((unsigned)__bfloat16_as_ushort(__float2bfloat16_rn(ry)) << 16);
}

__global__ __launch_bounds__(256) void hgemm_nt(const float* __restrict__ A,
                                                const float* __restrict__ B,
                                                float* __restrict__ C,
                                                int M, int Nn, int K)
{
    __shared__ unsigned short As_hi[BM * SST];
    __shared__ unsigned short As_lo[BM * SST];
    __shared__ unsigned short Bs_hi[BN * SST];
    __shared__ unsigned short Bs_lo[BN * SST];

    const int tid = threadIdx.x;
    const int lane = tid & 31;
    const int wid = tid >> 5;
    const int wm = wid >> 2;          // 0..1 -> m offset 64
    const int wn = wid & 3;           // 0..3 -> n offset 32
    const int mtile = blockIdx.y, ntile = blockIdx.x;

    const unsigned ahi = (unsigned)__cvta_generic_to_shared(As_hi);
    const unsigned alo = (unsigned)__cvta_generic_to_shared(As_lo);
    const unsigned bhi = (unsigned)__cvta_generic_to_shared(Bs_hi);
    const unsigned blo = (unsigned)__cvta_generic_to_shared(Bs_lo);

    // global tile load mapping: idx = tid + i*256 -> row = idx>>3, col = (idx&7)*4
    int lrow[4], lcol[4];
#pragma unroll
    for (int i = 0; i < 4; i++) {
        int idx = tid + i * 256;
        lrow[i] = idx >> 3;
        lcol[i] = (idx & 7) << 2;
    }
    const float* Ag = A + (size_t)(mtile * BM) * K;
    const float* Bg = B + (size_t)(ntile * BN) * K;

    float acc[4][4][4];
#pragma unroll
    for (int a = 0; a < 4; a++)
#pragma unroll
        for (int b = 0; b < 4; b++)
#pragma unroll
            for (int cc = 0; cc < 4; cc++) acc[a][b][cc] = 0.f;

    // fragment smem addresses (bytes)
    unsigned a_row = wm * 64 + (lane & 15);
    unsigned a_half = (lane >> 4) * 8;
    unsigned b_row = wn * 32 + (lane & 15);

    const int NC = K / BK;
    float4 bufA[4], bufB[4];

    // prefetch chunk 0
#pragma unroll
    for (int i = 0; i < 4; i++) {
        bufA[i] = *reinterpret_cast<const float4*>(Ag + (size_t)lrow[i] * K + lcol[i]);
        int grow = ntile * BN + lrow[i];
        bufB[i] = (grow < Nn)
                      ? *reinterpret_cast<const float4*>(Bg + (size_t)lrow[i] * K + lcol[i])
                      : make_float4(0.f, 0.f, 0.f, 0.f);
    }

    for (int c = 0; c < NC; c++) {
        // convert + store to smem
#pragma unroll
        for (int i = 0; i < 4; i++) {
            unsigned h0, l0, h1, l1;
            split2(bufA[i].x, bufA[i].y, h0, l0);
            split2(bufA[i].z, bufA[i].w, h1, l1);
            unsigned off = (unsigned)(lrow[i] * SST + lcol[i]) * 2;
            asm volatile("st.shared.v2.b32 [%0], {%1,%2};" :: "r"(ahi + off), "r"(h0), "r"(h1));
            asm volatile("st.shared.v2.b32 [%0], {%1,%2};" :: "r"(alo + off), "r"(l0), "r"(l1));
            split2(bufB[i].x, bufB[i].y, h0, l0);
            split2(bufB[i].z, bufB[i].w, h1, l1);
            asm volatile("st.shared.v2.b32 [%0], {%1,%2};" :: "r"(bhi + off), "r"(h0), "r"(h1));
            asm volatile("st.shared.v2.b32 [%0], {%1,%2};" :: "r"(blo + off), "r"(l0), "r"(l1));
        }
        __syncthreads();

        // prefetch next chunk (overlaps with mma below)
        if (c + 1 < NC) {
            int k0 = (c + 1) * BK;
#pragma unroll
            for (int i = 0; i < 4; i++) {
                bufA[i] = *reinterpret_cast<const float4*>(Ag + (size_t)lrow[i] * K + k0 + lcol[i]);
                int grow = ntile * BN + lrow[i];
                bufB[i] = (grow < Nn)
                              ? *reinterpret_cast<const float4*>(Bg + (size_t)lrow[i] * K + k0 + lcol[i])
                              : make_float4(0.f, 0.f, 0.f, 0.f);
            }
        }

#pragma unroll
        for (int ks = 0; ks < 2; ks++) {
            unsigned kk = ks * 16 + a_half;
            unsigned afr[4][4], bh2[2][4], bl2[2][4];
#pragma unroll
            for (int mt = 0; mt < 4; mt++)
                ldsm4(afr[mt], ahi + ((a_row + mt * 16) * SST + kk) * 2);
#pragma unroll
            for (int p = 0; p < 2; p++) {
                ldsm4(bh2[p], bhi + ((b_row + p * 16) * SST + kk) * 2);
                ldsm4(bl2[p], blo + ((b_row + p * 16) * SST + kk) * 2);
            }
            // pass 1: Ahi * Bhi
#pragma unroll
            for (int mt = 0; mt < 4; mt++)
#pragma unroll
                for (int nt = 0; nt < 4; nt++)
                    mma16816(acc[mt][nt], afr[mt],
                             bh2[nt >> 1][nt & 1], bh2[nt >> 1][2 + (nt & 1)]);
            // pass 2: Ahi * Blo
#pragma unroll
            for (int mt = 0; mt < 4; mt++)
#pragma unroll
                for (int nt = 0; nt < 4; nt++)
                    mma16816(acc[mt][nt], afr[mt],
                             bl2[nt >> 1][nt & 1], bl2[nt >> 1][2 + (nt & 1)]);
            // pass 3: Alo * Bhi
#pragma unroll
            for (int mt = 0; mt < 4; mt++)
                ldsm4(afr[mt], alo + ((a_row + mt * 16) * SST + kk) * 2);
#pragma unroll
            for (int mt = 0; mt < 4; mt++)
#pragma unroll
                for (int nt = 0; nt < 4; nt++)
                    mma16816(acc[mt][nt], afr[mt],
                             bh2[nt >> 1][nt & 1], bh2[nt >> 1][2 + (nt & 1)]);
        }
        __syncthreads();
    }

    // epilogue
#pragma unroll
    for (int mt = 0; mt < 4; mt++) {
        int grow = mtile * BM + wm * 64 + mt * 16 + (lane >> 2);
#pragma unroll
        for (int nt = 0; nt < 4; nt++) {
            int gcol = ntile * BN + wn * 32 + nt * 8 + (lane & 3) * 2;
            if (gcol < Nn) {
                float2 v0 = make_float2(acc[mt][nt][0], acc[mt][nt][1]);
                float2 v1 = make_float2(acc[mt][nt][2], acc[mt][nt][3]);
                *reinterpret_cast<float2*>(C + (size_t)grow * Nn + gcol) = v0;
                *reinterpret_cast<float2*>(C + (size_t)(grow + 8) * Nn + gcol) = v1;
            }
        }
    }
}

// ---------------- depthwise causal conv (K=4) + SiLU ----------------------------
__global__ __launch_bounds__(256) void conv_silu_kernel(const float* __restrict__ x,
                                                        const float* __restrict__ w,
                                                        float* __restrict__ y)
{
    int idx = blockIdx.x * blockDim.x + threadIdx.x;
    if (idx >= NTOK * PROJ) return;
    int n = idx / PROJ;
    int d = idx - n * PROJ;
    float acc = 0.f;
#pragma unroll
    for (int i = 0; i < CONVK; i++) {
        int nn = n - (CONVK - 1) + i;
        float xv = (nn >= 0) ? x[(long)nn * PROJ + d] : 0.f;
        acc = fmaf(xv, w[d * CONVK + i], acc);
    }
    y[idx] = acc / (1.f + expf(-acc));
}

// ---------------- per-(n,h): l2-normalize q,k; build g; sigmoid(beta) -----------
__global__ __launch_bounds__(128) void prep_kernel(float* __restrict__ q,
                                                   float* __restrict__ k,
                                                   float* __restrict__ g,
                                                   const float* __restrict__ betapre,
                                                   float* __restrict__ beta,
                                                   const float* __restrict__ A_log,
                                                   const float* __restrict__ dt_bias)
{
    const int row = blockIdx.x;          // n*NH + h
    const int hh = row & (NH - 1);
    const int tid = threadIdx.x;         // 0..127 = dk
    const long base = (long)row * DKD;

    float qv = q[base + tid];
    float kv = k[base + tid];
    float sq = qv * qv, sk = kv * kv;
#pragma unroll
    for (int o = 16; o > 0; o >>= 1) {
        sq += __shfl_xor_sync(0xffffffffu, sq, o);
        sk += __shfl_xor_sync(0xffffffffu, sk, o);
    }
    __shared__ float red[4][2];
    int wid = tid >> 5, lane = tid & 31;
    if (lane == 0) { red[wid][0] = sq; red[wid][1] = sk; }
    __syncthreads();
    float sumq = red[0][0] + red[1][0] + red[2][0] + red[3][0];
    float sumk = red[0][1] + red[1][1] + red[2][1] + red[3][1];

    q[base + tid] = qv * rsqrtf(sumq + 1e-6f) * 0.08838834764831845f; // * dk^-0.5
    k[base + tid] = kv * rsqrtf(sumk + 1e-6f);

    float fv = g[base + tid] + dt_bias[hh * DKD + tid];
    float sp = (fv > 20.f) ? fv : log1pf(expf(fv));
    g[base + tid] = -expf(A_log[hh]) * sp;

    if (tid == 0) beta[row] = 1.f / (1.f + expf(-betapre[row]));
}

// ---------------- sequential gated delta-rule scan ------------------------------
__global__ __launch_bounds__(256) void scan_kernel(const float* __restrict__ q,
                                                   const float* __restrict__ k,
                                                   const float* __restrict__ v,
                                                   const float* __restrict__ g,
                                                   const float* __restrict__ beta,
                                                   float* __restrict__ core)
{
    const int h  = blockIdx.x / VSPLIT;
    const int vb = (blockIdx.x % VSPLIT) * VCOLS;
    const int tid = threadIdx.x;
    const int vc = tid & 31;
    const int kg = tid >> 5;
    const int kbase = kg * 16;

    __shared__ float sk[DKD], sq[DKD], seg[DKD];
    __shared__ float sv[VCOLS], sdelta[VCOLS];
    __shared__ float red[8][VCOLS];
    __shared__ float sbeta;

    float s[16];
#pragma unroll
    for (int i = 0; i < 16; i++) s[i] = 0.f;

    const int hb = h * DKD;
    for (int t = 0; t < NTOK; t++) {
        const long off = (long)t * PROJ + hb;
        if (tid < DKD) {
            sk[tid] = k[off + tid];
            sq[tid] = q[off + tid];
            seg[tid] = expf(g[off + tid]);
        } else if (tid < DKD + VCOLS) {
            sv[tid - DKD] = v[off + vb + (tid - DKD)];
        } else if (tid == DKD + VCOLS) {
            sbeta = beta[t * NH + h];
        }
        __syncthreads();

        float kreg[16];
        float acc = 0.f;
#pragma unroll
        for (int i = 0; i < 16; i++) {
            int kk = kbase + i;
            float kv_ = sk[kk];
            kreg[i] = kv_;
            float sn = s[i] * seg[kk];
            s[i] = sn;
            acc = fmaf(kv_, sn, acc);
        }
        red[kg][vc] = acc;
        __syncthreads();

        if (kg == 0) {
            float kvs = red[0][vc] + red[1][vc] + red[2][vc] + red[3][vc]
                      + red[4][vc] + red[5][vc] + red[6][vc] + red[7][vc];
            sdelta[vc] = (sv[vc] - kvs) * sbeta;
        }
        __syncthreads();

        float delta = sdelta[vc];
        float oacc = 0.f;
#pragma unroll
        for (int i = 0; i < 16; i++) {
            int kk = kbase + i;
            float sn = fmaf(kreg[i], delta, s[i]);
            s[i] = sn;
            oacc = fmaf(sq[kk], sn, oacc);
        }
        red[kg][vc] = oacc;
        __syncthreads();

        if (kg == 0) {
            float osum = red[0][vc] + red[1][vc] + red[2][vc] + red[3][vc]
                       + red[4][vc] + red[5][vc] + red[6][vc] + red[7][vc];
            core[off + vb + vc] = osum;
        }
        __syncthreads();
    }
}

// ---------------- gated RMSNorm (sigmoid gate) -----------------------------------
__global__ __launch_bounds__(128) void rmsgate_kernel(const float* __restrict__ core,
                                                      const float* __restrict__ gate,
                                                      const float* __restrict__ onorm_w,
                                                      float* __restrict__ rg)
{
    const int row = blockIdx.x;          // n*NH + h
    const int tid = threadIdx.x;
    const long base = (long)row * DKD;

    float c = core[base + tid];
    float ss = c * c;
#pragma unroll
    for (int o = 16; o > 0; o >>= 1)
        ss += __shfl_xor_sync(0xffffffffu, ss, o);
    __shared__ float red[4];
    int wid = tid >> 5, lane = tid & 31;
    if (lane == 0) red[wid] = ss;
    __syncthreads();
    float sum = red[0] + red[1] + red[2] + red[3];

    float rms = c * rsqrtf(sum * (1.f / DKD) + 1e-5f);
    float gt = gate[base + tid];
    rg[base + tid] = rms * onorm_w[tid] * (1.f / (1.f + expf(-gt)));
}

// ---------------- launch ---------------------------------------------------------
extern "C" void kernel_launch(void* const* d_in, const int* in_sizes, int n_in,
                              void* d_out, int out_size)
{
    const float* hs   = (const float*)d_in[0];
    const float* Wq   = (const float*)d_in[1];
    const float* Wk   = (const float*)d_in[2];
    const float* Wv   = (const float*)d_in[3];
    const float* cq   = (const float*)d_in[4];
    const float* ck   = (const float*)d_in[5];
    const float* cv   = (const float*)d_in[6];
    const float* Wfa  = (const float*)d_in[7];
    const float* Wfb  = (const float*)d_in[8];
    const float* dtb  = (const float*)d_in[9];
    const float* Wb   = (const float*)d_in[10];
    const float* Alog = (const float*)d_in[11];
    const float* Wga  = (const float*)d_in[12];
    const float* Wgb  = (const float*)d_in[13];
    const float* onw  = (const float*)d_in[14];
    const float* Wo   = (const float*)d_in[15];
    float* out = (float*)d_out;

    float *qpre, *kpre, *vpre, *qb, *kb, *vbuf, *gb, *gateb, *fa, *ga, *betapre, *betab;
    cudaGetSymbolAddress((void**)&qpre, g_qpre);
    cudaGetSymbolAddress((void**)&kpre, g_kpre);
    cudaGetSymbolAddress((void**)&vpre, g_vpre);
    cudaGetSymbolAddress((void**)&qb,   g_qb);
    cudaGetSymbolAddress((void**)&kb,   g_kb);
    cudaGetSymbolAddress((void**)&vbuf, g_vb);
    cudaGetSymbolAddress((void**)&gb,   g_gb);
    cudaGetSymbolAddress((void**)&gateb,g_gate);
    cudaGetSymbolAddress((void**)&fa,   g_fa);
    cudaGetSymbolAddress((void**)&ga,   g_ga);
    cudaGetSymbolAddress((void**)&betapre, g_betapre);
    cudaGetSymbolAddress((void**)&betab,   g_beta);

    float* core = kpre;  // kpre dead after conv
    float* rg   = qpre;  // qpre dead after conv

    dim3 blk(256);
    auto gg = [](int M, int Nn) {
        return dim3((unsigned)((Nn + BN - 1) / BN), (unsigned)(M / BM));
    };

    // projections (bf16-split HMMA)
    hgemm_nt<<<gg(NTOK, PROJ), blk>>>(hs, Wq, qpre, NTOK, PROJ, HIDDIM);
    hgemm_nt<<<gg(NTOK, PROJ), blk>>>(hs, Wk, kpre, NTOK, PROJ, HIDDIM);
    hgemm_nt<<<gg(NTOK, PROJ), blk>>>(hs, Wv, vpre, NTOK, PROJ, HIDDIM);
    hgemm_nt<<<gg(NTOK, DKD),  blk>>>(hs, Wfa, fa, NTOK, DKD, HIDDIM);
    hgemm_nt<<<gg(NTOK, NH),   blk>>>(hs, Wb, betapre, NTOK, NH, HIDDIM);
    hgemm_nt<<<gg(NTOK, DKD),  blk>>>(hs, Wga, ga, NTOK, DKD, HIDDIM);

    // conv + silu (frees kpre/qpre for reuse)
    int ce = NTOK * PROJ;
    conv_silu_kernel<<<(ce + 255) / 256, 256>>>(qpre, cq, qb);
    conv_silu_kernel<<<(ce + 255) / 256, 256>>>(kpre, ck, kb);
    conv_silu_kernel<<<(ce + 255) / 256, 256>>>(vpre, cv, vbuf);

    // low-rank expansions (K=128)
    hgemm_nt<<<gg(NTOK, PROJ), blk>>>(fa, Wfb, gb,    NTOK, PROJ, DKD);
    hgemm_nt<<<gg(NTOK, PROJ), blk>>>(ga, Wgb, gateb, NTOK, PROJ, DKD);

    // normalize q/k, build g and beta
    prep_kernel<<<NTOK * NH, 128>>>(qb, kb, gb, betapre, betab, Alog, dtb);

    // recurrent delta-rule scan
    scan_kernel<<<NH * VSPLIT, 256>>>(qb, kb, vbuf, gb, betab, core);

    // gated rmsnorm
    rmsgate_kernel<<<NTOK * NH, 128>>>(core, gateb, onw, rg);

    // output projection
    hgemm_nt<<<gg(NTOK, HIDDIM), blk>>>(rg, Wo, out, NTOK, HIDDIM, PROJ);
}